// round 15
// baseline (speedup 1.0000x reference)
#include <cuda_runtime.h>
#include <cuda_bf16.h>
#include <cstdint>

#define BATCH   32768
#define D_IN    160
#define D_H1    512
#define D_H2    1024
#define D_OUT   3072

// ---------------- scratch (static device arrays; allocation-free) -----------
// GEMM operands in bf16, K-permuted per 32-element block:
// element k lives at pos = ((k>>1)&3)*8 + ((k>>3)<<1) + (k&1)  (involution).
__device__ __nv_bfloat16 g_xm[BATCH * D_IN];    // 10 MB  masked input, K-perm
__device__ __nv_bfloat16 g_h1[BATCH * D_H1];    // 32 MB
__device__ __nv_bfloat16 g_h2[BATCH * D_H2];    // 64 MB
__device__ __nv_bfloat16 g_w1t[D_H1 * D_IN];    // W1^T [512,160], K-perm
__device__ __nv_bfloat16 g_w2t[D_H2 * D_H1];    // W2^T [1024,512], K-perm
__device__ __nv_bfloat16 g_w3t[D_OUT * D_H2];   // W3^T [3072,1024], K-perm

// ---------------- helpers ---------------------------------------------------
__device__ __forceinline__ uint32_t smem_u32(const void* p) {
    uint32_t a;
    asm("{ .reg .u64 t; cvta.to.shared.u64 t, %1; cvt.u32.u64 %0, t; }" : "=r"(a) : "l"(p));
    return a;
}
__device__ __forceinline__ int kperm32(int k) {           // k in [0,32), involution
    return ((k >> 1) & 3) * 8 + ((k >> 3) << 1) + (k & 1);
}
__device__ __forceinline__ void cp16(uint32_t dst, const void* src) {
    asm volatile("cp.async.cg.shared.global [%0], [%1], 16;" :: "r"(dst), "l"(src));
}
#define CP_COMMIT()  asm volatile("cp.async.commit_group;" ::: "memory")
#define CP_WAIT(n)   asm volatile("cp.async.wait_group %0;" :: "n"(n) : "memory")

__device__ __forceinline__ void mma_bf16(float* c,
                                         uint32_t a0, uint32_t a1, uint32_t a2, uint32_t a3,
                                         uint32_t b0, uint32_t b1) {
    asm volatile(
        "mma.sync.aligned.m16n8k16.row.col.f32.bf16.bf16.f32 "
        "{%0,%1,%2,%3}, {%4,%5,%6,%7}, {%8,%9}, {%0,%1,%2,%3};"
        : "+f"(c[0]), "+f"(c[1]), "+f"(c[2]), "+f"(c[3])
        : "r"(a0), "r"(a1), "r"(a2), "r"(a3), "r"(b0), "r"(b1));
}

// ---------------- GEMM config ----------------------------------------------
#define BM 128
#define BN 128
#define BK 32
#define STAGES 6
#define PFD 4                                      // prefetch distance (tiles)
#define STAGE_BYTES (2 * BM * BK * 2)              // 16384 (A 8K + B 8K)
#define SMEM_BIAS   0
#define SMEM_TILES  1024
#define SMEM_DYN    (SMEM_TILES + STAGES * STAGE_BYTES)   // 99328 -> 2 CTAs/SM
#define GROUP_M 16

// ---------------------------------------------------------------------------
// Pipelined bf16 mma.sync GEMM (champion schedule + interleaved prefetch):
// 128 threads, 4 warps (2x2), warp tile 64x64, 6-stage cp.async pipeline,
// prefetch distance 4, __syncthreads only every SECOND K-tile, register
// fragments preloaded across the barrier, fp32 accumulate, 2 CTAs/SM.
// NEW: the 8 cp.async per tile are interleaved into the 64-HMMA stream
// (1 per 8 HMMAs) instead of bursting at loop head — LDGSTS issue
// backpressure (rt=8/SMSP) hides under tensor-pipe dispatch gaps.
// ACT: 0 = relu, bf16 K-permuted stores;  1 = sigmoid, fp32 stores
// ---------------------------------------------------------------------------
template <int ACT>
__global__ __launch_bounds__(128, 2)
void gemm_bf16(const __nv_bfloat16* __restrict__ A, const __nv_bfloat16* __restrict__ Bt,
               const float* __restrict__ bias, void* __restrict__ Cv,
               int M, int N, int K)
{
    extern __shared__ char smem[];
    float* bias_s = (float*)(smem + SMEM_BIAS);
    const uint32_t tiles_u32 = smem_u32(smem + SMEM_TILES);

    const int tid  = threadIdx.x;
    const int wid  = tid >> 5, lane = tid & 31;
    const int g    = lane >> 2, tg = lane & 3;
    const int wm   = wid & 1, wn = wid >> 1;          // 2 x 2 warp grid

    // grouped rasterization
    const int num_n = N / BN;
    const int tpg   = GROUP_M * num_n;
    const int grp   = blockIdx.x / tpg;
    const int rem   = blockIdx.x % tpg;
    const int m0 = (grp * GROUP_M + rem % GROUP_M) * BM;
    const int n0 = (rem / GROUP_M) * BN;

    bias_s[tid] = bias[n0 + tid];

    const int KT = K / BK;

    // one 16B cp.async of a stage: j in [0,8); j<4 -> A chunk, else B chunk.
    auto cp_one = [&](int s, int kt, int j) {
        const uint32_t base = tiles_u32 + s * STAGE_BYTES;
        const int cg = tid & 3;
        if (j < 4) {
            const int row = (tid + j * 128) >> 2;
            cp16(base + row * 64 + cg * 16,
                 A + (size_t)(m0 + row) * K + kt * BK + cg * 8);
        } else {
            const int row = (tid + (j - 4) * 128) >> 2;
            cp16(base + 8192 + row * 64 + cg * 16,
                 Bt + (size_t)(n0 + row) * K + kt * BK + cg * 8);
        }
    };
    auto load_stage = [&](int s, int kt) {
        #pragma unroll
        for (int j = 0; j < 8; j++) cp_one(s, kt, j);
    };

    // fragment loader: all frags for one tile from stage s (16 LDS.128)
    uint4 a[4][2], b[2][4];
    auto frag_load = [&](int s) {
        const uint4* As4 = (const uint4*)(smem + SMEM_TILES + s * STAGE_BYTES);
        const uint4* Bs4 = As4 + 512;
        #pragma unroll
        for (int im = 0; im < 4; im++)
            #pragma unroll
            for (int h = 0; h < 2; h++)
                a[im][h] = As4[(wm * 64 + im * 16 + h * 8 + g) * 4 + tg];
        #pragma unroll
        for (int half = 0; half < 2; half++)
            #pragma unroll
            for (int i = 0; i < 4; i++)
                b[half][i] = Bs4[(wn * 64 + half * 32 + i * 8 + g) * 4 + tg];
    };

    // prologue: fill PFD stages, then pre-load frags for tile 0
    #pragma unroll
    for (int s = 0; s < PFD; s++) { load_stage(s, s); CP_COMMIT(); }
    CP_WAIT(PFD - 1);                 // tile 0 arrived
    __syncthreads();
    frag_load(0);

    float acc[4][8][4];
    #pragma unroll
    for (int im = 0; im < 4; im++)
        #pragma unroll
        for (int in = 0; in < 8; in++)
            #pragma unroll
            for (int q = 0; q < 4; q++) acc[im][in][q] = 0.f;

    int cs = 0;                       // stage holding tile kt's data
    int ps = PFD;                     // stage to prefetch into
    for (int kt = 0; kt < KT; kt++) {
        if (!(kt & 1)) __syncthreads();   // protects slot reuse (2-iter window)

        const int kn = kt + PFD;
        const bool pf = (kn < KT);

        // compute: 64 HMMA on pre-loaded frags, with one cp.async slipped in
        // after every 4th mma-pair (8 HMMAs) when prefetching.
        #pragma unroll
        for (int half = 0; half < 2; half++)
            #pragma unroll
            for (int im = 0; im < 4; im++)
                #pragma unroll
                for (int i = 0; i < 4; i++) {
                    float* c = acc[im][half * 4 + i];
                    mma_bf16(c, a[im][0].x, a[im][1].x, a[im][0].y, a[im][1].y,
                             b[half][i].x, b[half][i].y);
                    mma_bf16(c, a[im][0].z, a[im][1].z, a[im][0].w, a[im][1].w,
                             b[half][i].z, b[half][i].w);
                    const int idx = half * 16 + im * 4 + i;       // 0..31
                    if (((idx & 3) == 3) && pf) cp_one(ps, kn, idx >> 2);
                }
        CP_COMMIT();                      // group for tile kn (possibly empty)
        if (++ps == STAGES) ps = 0;

        if (++cs == STAGES) cs = 0;
        if (kt + 1 < KT) {
            CP_WAIT(3);                   // tile kt+1 resident
            frag_load(cs);                // tail LDS overlap next iter's MMAs
        }
    }

    // -------- epilogue -----------------------------------------------------
    #pragma unroll
    for (int im = 0; im < 4; im++) {
        #pragma unroll
        for (int in = 0; in < 8; in++) {
            const int cl = wn * 64 + in * 8 + 2 * tg;
            #pragma unroll
            for (int h = 0; h < 2; h++) {
                const int row = m0 + wm * 64 + im * 16 + g + 8 * h;
                float v0 = acc[im][in][2 * h]     + bias_s[cl];
                float v1 = acc[im][in][2 * h + 1] + bias_s[cl + 1];
                if (ACT == 0) {
                    v0 = fmaxf(v0, 0.f);
                    v1 = fmaxf(v1, 0.f);
                    const int c0 = n0 + cl;                     // even
                    const int kk = c0 & 31;
                    const int pos = (c0 & ~31) + ((kk >> 1) & 3) * 8 + ((kk >> 3) << 1);
                    *(__nv_bfloat162*)((__nv_bfloat16*)Cv + (size_t)row * N + pos) =
                        __floats2bfloat162_rn(v0, v1);
                } else {
                    v0 = 1.f / (1.f + __expf(-v0));
                    v1 = 1.f / (1.f + __expf(-v1));
                    *(float2*)((float*)Cv + (size_t)row * N + n0 + cl) =
                        make_float2(v0, v1);
                }
            }
        }
    }
}

// ---------------------------------------------------------------------------
// Mask build: warp per row. Computes argmax capsule by L2 norm, then writes
// the masked input as bf16 in K-perm32 layout (kperm32 is an involution, so
// a shuffle from lane kperm32(lane) produces the value for position lane).
// ---------------------------------------------------------------------------
__global__ __launch_bounds__(256)
void mask_build_kernel(const float* __restrict__ x)
{
    const int warp = threadIdx.x >> 5, lane = threadIdx.x & 31;
    const int bi = blockIdx.x * 8 + warp;
    const float* xr = x + (size_t)bi * D_IN;

    float xv[5];
    #pragma unroll
    for (int q = 0; q < 5; q++) xv[q] = xr[q * 32 + lane];

    // capsule norms: for each q, lanes [0,16) hold capsule 2q, [16,32) 2q+1
    float bestv = -1.f; int bestj = 0;
    #pragma unroll
    for (int q = 0; q < 5; q++) {
        float s = xv[q] * xv[q];
        s += __shfl_xor_sync(~0u, s, 1);
        s += __shfl_xor_sync(~0u, s, 2);
        s += __shfl_xor_sync(~0u, s, 4);
        s += __shfl_xor_sync(~0u, s, 8);
        const int j = 2 * q + (lane >> 4);
        if (s > bestv) { bestv = s; bestj = j; }      // ascending j: > keeps first
    }
    {
        const float ov = __shfl_xor_sync(~0u, bestv, 16);
        const int   oj = __shfl_xor_sync(~0u, bestj, 16);
        if (ov > bestv || (ov == bestv && oj < bestj)) { bestv = ov; bestj = oj; }
    }
    const int jm = bestj;                              // uniform across warp

    const int kl = kperm32(lane);                      // source k within block
    __nv_bfloat16* out = g_xm + (size_t)bi * D_IN;
    #pragma unroll
    for (int q = 0; q < 5; q++) {
        const float val = __shfl_sync(~0u, xv[q], kl);
        const int cap = 2 * q + (kl >> 4);
        out[q * 32 + lane] = (cap == jm) ? __float2bfloat16_rn(val)
                                         : __float2bfloat16_rn(0.f);
    }
}

// ---------------------------------------------------------------------------
// Fused transpose + bf16 + K-perm for ALL THREE weights in one launch.
// z selects the weight; per-z (K,N) dims; grid sized for the largest and
// blocks outside a weight's range exit early.
//   z=0: W1 [160,512] -> w1t;  z=1: W2 [512,1024] -> w2t;  z=2: W3 [1024,3072] -> w3t
// ---------------------------------------------------------------------------
__global__ void transpose_all_kernel(const float* __restrict__ W1,
                                     const float* __restrict__ W2,
                                     const float* __restrict__ W3)
{
    const float* W;
    __nv_bfloat16* Wt;
    int K, N;
    if (blockIdx.z == 0)      { W = W1; Wt = g_w1t; K = D_IN;  N = D_H1; }
    else if (blockIdx.z == 1) { W = W2; Wt = g_w2t; K = D_H1;  N = D_H2; }
    else                      { W = W3; Wt = g_w3t; K = D_H2;  N = D_OUT; }

    const int k0 = blockIdx.y * 32, n0 = blockIdx.x * 32;
    if (k0 >= K || n0 >= N) return;

    __shared__ float t[32][33];
    #pragma unroll
    for (int j = 0; j < 4; j++) {
        int k = threadIdx.y + j * 8;
        t[k][threadIdx.x] = W[(size_t)(k0 + k) * N + n0 + threadIdx.x];
    }
    __syncthreads();
    #pragma unroll
    for (int j = 0; j < 4; j++) {
        int n = threadIdx.y + j * 8;
        int kk = k0 + threadIdx.x;
        Wt[(size_t)(n0 + n) * K + (kk & ~31) + kperm32(kk & 31)] =
            __float2bfloat16_rn(t[threadIdx.x][n]);
    }
}

// ---------------------------------------------------------------------------
extern "C" void kernel_launch(void* const* d_in, const int* in_sizes, int n_in,
                              void* d_out, int out_size)
{
    const float* x  = (const float*)d_in[0];
    const float* W1 = (const float*)d_in[2];
    const float* b1 = (const float*)d_in[3];
    const float* W2 = (const float*)d_in[4];
    const float* b2 = (const float*)d_in[5];
    const float* W3 = (const float*)d_in[6];
    const float* b3 = (const float*)d_in[7];
    float* out = (float*)d_out;

    __nv_bfloat16 *xm, *h1, *h2, *w1t, *w2t, *w3t;
    cudaGetSymbolAddress((void**)&xm,  g_xm);
    cudaGetSymbolAddress((void**)&h1,  g_h1);
    cudaGetSymbolAddress((void**)&h2,  g_h2);
    cudaGetSymbolAddress((void**)&w1t, g_w1t);
    cudaGetSymbolAddress((void**)&w2t, g_w2t);
    cudaGetSymbolAddress((void**)&w3t, g_w3t);

    cudaFuncSetAttribute(gemm_bf16<0>, cudaFuncAttributeMaxDynamicSharedMemorySize, SMEM_DYN);
    cudaFuncSetAttribute(gemm_bf16<1>, cudaFuncAttributeMaxDynamicSharedMemorySize, SMEM_DYN);

    // all weight packs in one launch (grid sized for W3: 3072/32 x 1024/32)
    transpose_all_kernel<<<dim3(D_OUT / 32, D_H2 / 32, 3), dim3(32, 8)>>>(W1, W2, W3);

    // masked input (bf16, K-perm)
    mask_build_kernel<<<BATCH / 8, 256>>>(x);

    // h1 = relu(xm @ W1 + b1), bf16 K-permuted   [32768,512] K=160 (KT=5)
    gemm_bf16<0><<<(BATCH / BM) * (D_H1 / BN), 128, SMEM_DYN>>>(
        xm, w1t, b1, h1, BATCH, D_H1, D_IN);

    // h2 = relu(h1 @ W2 + b2), bf16 K-permuted
    gemm_bf16<0><<<(BATCH / BM) * (D_H2 / BN), 128, SMEM_DYN>>>(
        h1, w2t, b2, h2, BATCH, D_H2, D_H1);

    // out = sigmoid(h2 @ W3 + b3), fp32
    gemm_bf16<1><<<(BATCH / BM) * (D_OUT / BN), 128, SMEM_DYN>>>(
        h2, w3t, b3, out, BATCH, D_OUT, D_H2);
}

// round 16
// speedup vs baseline: 1.0512x; 1.0512x over previous
#include <cuda_runtime.h>
#include <cuda_bf16.h>
#include <cstdint>

#define BATCH   32768
#define D_IN    160
#define D_H1    512
#define D_H2    1024
#define D_OUT   3072

// ---------------- scratch (static device arrays; allocation-free) -----------
// GEMM operands in bf16, K-permuted per 32-element block:
// element k lives at pos = ((k>>1)&3)*8 + ((k>>3)<<1) + (k&1)  (involution).
__device__ __nv_bfloat16 g_xm[BATCH * D_IN];    // 10 MB  masked input, K-perm
__device__ __nv_bfloat16 g_h1[BATCH * D_H1];    // 32 MB
__device__ __nv_bfloat16 g_h2[BATCH * D_H2];    // 64 MB
__device__ __nv_bfloat16 g_w1t[D_H1 * D_IN];    // W1^T [512,160], K-perm
__device__ __nv_bfloat16 g_w2t[D_H2 * D_H1];    // W2^T [1024,512], K-perm
__device__ __nv_bfloat16 g_w3t[D_OUT * D_H2];   // W3^T [3072,1024], K-perm

// ---------------- helpers ---------------------------------------------------
__device__ __forceinline__ uint32_t smem_u32(const void* p) {
    uint32_t a;
    asm("{ .reg .u64 t; cvta.to.shared.u64 t, %1; cvt.u32.u64 %0, t; }" : "=r"(a) : "l"(p));
    return a;
}
__device__ __forceinline__ int kperm32(int k) {           // k in [0,32), involution
    return ((k >> 1) & 3) * 8 + ((k >> 3) << 1) + (k & 1);
}
__device__ __forceinline__ void cp16(uint32_t dst, const void* src) {
    asm volatile("cp.async.cg.shared.global [%0], [%1], 16;" :: "r"(dst), "l"(src));
}
#define CP_COMMIT()  asm volatile("cp.async.commit_group;" ::: "memory")
#define CP_WAIT(n)   asm volatile("cp.async.wait_group %0;" :: "n"(n) : "memory")

__device__ __forceinline__ void mma_bf16(float* c,
                                         uint32_t a0, uint32_t a1, uint32_t a2, uint32_t a3,
                                         uint32_t b0, uint32_t b1) {
    asm volatile(
        "mma.sync.aligned.m16n8k16.row.col.f32.bf16.bf16.f32 "
        "{%0,%1,%2,%3}, {%4,%5,%6,%7}, {%8,%9}, {%0,%1,%2,%3};"
        : "+f"(c[0]), "+f"(c[1]), "+f"(c[2]), "+f"(c[3])
        : "r"(a0), "r"(a1), "r"(a2), "r"(a3), "r"(b0), "r"(b1));
}

// ---------------- GEMM config ----------------------------------------------
#define BM 128
#define BN 128
#define BK 32
#define STAGES 6
#define PFD 4                                      // prefetch distance (tiles)
#define STAGE_BYTES (2 * BM * BK * 2)              // 16384 (A 8K + B 8K)
#define SMEM_BIAS   0
#define SMEM_TILES  1024
#define SMEM_DYN    (SMEM_TILES + STAGES * STAGE_BYTES)   // 99328 -> 2 CTAs/SM
#define GROUP_M 16

// ---------------------------------------------------------------------------
// Pipelined bf16 mma.sync GEMM (round-14 champion schedule, verbatim):
// 128 threads, 4 warps (2x2), warp tile 64x64, 6-stage cp.async pipeline,
// prefetch distance 4, __syncthreads only every SECOND K-tile, register
// fragments preloaded across the barrier, fp32 accumulate, 2 CTAs/SM.
// ACT: 0 = relu, bf16 K-permuted stores;  1 = sigmoid, fp32 stores
// ---------------------------------------------------------------------------
template <int ACT>
__global__ __launch_bounds__(128, 2)
void gemm_bf16(const __nv_bfloat16* __restrict__ A, const __nv_bfloat16* __restrict__ Bt,
               const float* __restrict__ bias, void* __restrict__ Cv,
               int M, int N, int K)
{
    extern __shared__ char smem[];
    float* bias_s = (float*)(smem + SMEM_BIAS);
    const uint32_t tiles_u32 = smem_u32(smem + SMEM_TILES);

    const int tid  = threadIdx.x;
    const int wid  = tid >> 5, lane = tid & 31;
    const int g    = lane >> 2, tg = lane & 3;
    const int wm   = wid & 1, wn = wid >> 1;          // 2 x 2 warp grid

    // grouped rasterization
    const int num_n = N / BN;
    const int tpg   = GROUP_M * num_n;
    const int grp   = blockIdx.x / tpg;
    const int rem   = blockIdx.x % tpg;
    const int m0 = (grp * GROUP_M + rem % GROUP_M) * BM;
    const int n0 = (rem / GROUP_M) * BN;

    bias_s[tid] = bias[n0 + tid];

    const int KT = K / BK;

    // stage loader: 4 A + 4 B 16B chunks per thread; consecutive lanes ->
    // consecutive 16B of one 64B row (full-sector coalescing).
    auto load_stage = [&](int s, int kt) {
        const uint32_t base = tiles_u32 + s * STAGE_BYTES;
        const int cg = tid & 3;
        #pragma unroll
        for (int j = 0; j < 4; j++) {
            const int row = (tid + j * 128) >> 2;
            cp16(base + row * 64 + cg * 16,
                 A + (size_t)(m0 + row) * K + kt * BK + cg * 8);
            cp16(base + 8192 + row * 64 + cg * 16,
                 Bt + (size_t)(n0 + row) * K + kt * BK + cg * 8);
        }
    };

    // fragment loader: all frags for one tile from stage s (16 LDS.128)
    uint4 a[4][2], b[2][4];
    auto frag_load = [&](int s) {
        const uint4* As4 = (const uint4*)(smem + SMEM_TILES + s * STAGE_BYTES);
        const uint4* Bs4 = As4 + 512;
        #pragma unroll
        for (int im = 0; im < 4; im++)
            #pragma unroll
            for (int h = 0; h < 2; h++)
                a[im][h] = As4[(wm * 64 + im * 16 + h * 8 + g) * 4 + tg];
        #pragma unroll
        for (int half = 0; half < 2; half++)
            #pragma unroll
            for (int i = 0; i < 4; i++)
                b[half][i] = Bs4[(wn * 64 + half * 32 + i * 8 + g) * 4 + tg];
    };

    // prologue: fill PFD stages, then pre-load frags for tile 0
    #pragma unroll
    for (int s = 0; s < PFD; s++) { load_stage(s, s); CP_COMMIT(); }
    CP_WAIT(PFD - 1);                 // tile 0 arrived
    __syncthreads();
    frag_load(0);

    float acc[4][8][4];
    #pragma unroll
    for (int im = 0; im < 4; im++)
        #pragma unroll
        for (int in = 0; in < 8; in++)
            #pragma unroll
            for (int q = 0; q < 4; q++) acc[im][in][q] = 0.f;

    int cs = 0;                       // stage holding tile kt's data
    int ps = PFD;                     // stage to prefetch into
    for (int kt = 0; kt < KT; kt++) {
        if (!(kt & 1)) __syncthreads();   // protects slot reuse (2-iter window)

        const int kn = kt + PFD;
        if (kn < KT) load_stage(ps, kn);
        CP_COMMIT();
        if (++ps == STAGES) ps = 0;

        // compute: 64 HMMA on pre-loaded frags — issueable immediately
        #pragma unroll
        for (int half = 0; half < 2; half++)
            #pragma unroll
            for (int im = 0; im < 4; im++)
                #pragma unroll
                for (int i = 0; i < 4; i++) {
                    float* c = acc[im][half * 4 + i];
                    mma_bf16(c, a[im][0].x, a[im][1].x, a[im][0].y, a[im][1].y,
                             b[half][i].x, b[half][i].y);
                    mma_bf16(c, a[im][0].z, a[im][1].z, a[im][0].w, a[im][1].w,
                             b[half][i].z, b[half][i].w);
                }

        if (++cs == STAGES) cs = 0;
        if (kt + 1 < KT) {
            CP_WAIT(3);                   // tile kt+1 resident
            frag_load(cs);                // tail LDS overlap next iter's MMAs
        }
    }

    // -------- epilogue -----------------------------------------------------
    #pragma unroll
    for (int im = 0; im < 4; im++) {
        #pragma unroll
        for (int in = 0; in < 8; in++) {
            const int cl = wn * 64 + in * 8 + 2 * tg;
            #pragma unroll
            for (int h = 0; h < 2; h++) {
                const int row = m0 + wm * 64 + im * 16 + g + 8 * h;
                float v0 = acc[im][in][2 * h]     + bias_s[cl];
                float v1 = acc[im][in][2 * h + 1] + bias_s[cl + 1];
                if (ACT == 0) {
                    v0 = fmaxf(v0, 0.f);
                    v1 = fmaxf(v1, 0.f);
                    const int c0 = n0 + cl;                     // even
                    const int kk = c0 & 31;
                    const int pos = (c0 & ~31) + ((kk >> 1) & 3) * 8 + ((kk >> 3) << 1);
                    *(__nv_bfloat162*)((__nv_bfloat16*)Cv + (size_t)row * N + pos) =
                        __floats2bfloat162_rn(v0, v1);
                } else {
                    v0 = 1.f / (1.f + __expf(-v0));
                    v1 = 1.f / (1.f + __expf(-v1));
                    *(float2*)((float*)Cv + (size_t)row * N + n0 + cl) =
                        make_float2(v0, v1);
                }
            }
        }
    }
}

// ---------------------------------------------------------------------------
// Mask build: warp per row. Computes argmax capsule by L2 norm, then writes
// the masked input as bf16 in K-perm32 layout (kperm32 is an involution, so
// a shuffle from lane kperm32(lane) produces the value for position lane).
// ---------------------------------------------------------------------------
__global__ __launch_bounds__(256)
void mask_build_kernel(const float* __restrict__ x)
{
    const int warp = threadIdx.x >> 5, lane = threadIdx.x & 31;
    const int bi = blockIdx.x * 8 + warp;
    const float* xr = x + (size_t)bi * D_IN;

    float xv[5];
    #pragma unroll
    for (int q = 0; q < 5; q++) xv[q] = xr[q * 32 + lane];

    // capsule norms: for each q, lanes [0,16) hold capsule 2q, [16,32) 2q+1
    float bestv = -1.f; int bestj = 0;
    #pragma unroll
    for (int q = 0; q < 5; q++) {
        float s = xv[q] * xv[q];
        s += __shfl_xor_sync(~0u, s, 1);
        s += __shfl_xor_sync(~0u, s, 2);
        s += __shfl_xor_sync(~0u, s, 4);
        s += __shfl_xor_sync(~0u, s, 8);
        const int j = 2 * q + (lane >> 4);
        if (s > bestv) { bestv = s; bestj = j; }      // ascending j: > keeps first
    }
    {
        const float ov = __shfl_xor_sync(~0u, bestv, 16);
        const int   oj = __shfl_xor_sync(~0u, bestj, 16);
        if (ov > bestv || (ov == bestv && oj < bestj)) { bestv = ov; bestj = oj; }
    }
    const int jm = bestj;                              // uniform across warp

    const int kl = kperm32(lane);                      // source k within block
    __nv_bfloat16* out = g_xm + (size_t)bi * D_IN;
    #pragma unroll
    for (int q = 0; q < 5; q++) {
        const float val = __shfl_sync(~0u, xv[q], kl);
        const int cap = 2 * q + (kl >> 4);
        out[q * 32 + lane] = (cap == jm) ? __float2bfloat16_rn(val)
                                         : __float2bfloat16_rn(0.f);
    }
}

// ---------------------------------------------------------------------------
// Fused transpose + bf16 + K-perm for ALL THREE weights in one launch.
// z selects the weight; blocks outside a weight's range exit early.
//   z=0: W1 [160,512] -> w1t;  z=1: W2 [512,1024] -> w2t;  z=2: W3 [1024,3072] -> w3t
// ---------------------------------------------------------------------------
__global__ void transpose_all_kernel(const float* __restrict__ W1,
                                     const float* __restrict__ W2,
                                     const float* __restrict__ W3)
{
    const float* W;
    __nv_bfloat16* Wt;
    int K, N;
    if (blockIdx.z == 0)      { W = W1; Wt = g_w1t; K = D_IN;  N = D_H1; }
    else if (blockIdx.z == 1) { W = W2; Wt = g_w2t; K = D_H1;  N = D_H2; }
    else                      { W = W3; Wt = g_w3t; K = D_H2;  N = D_OUT; }

    const int k0 = blockIdx.y * 32, n0 = blockIdx.x * 32;
    if (k0 >= K || n0 >= N) return;

    __shared__ float t[32][33];
    #pragma unroll
    for (int j = 0; j < 4; j++) {
        int k = threadIdx.y + j * 8;
        t[k][threadIdx.x] = W[(size_t)(k0 + k) * N + n0 + threadIdx.x];
    }
    __syncthreads();
    #pragma unroll
    for (int j = 0; j < 4; j++) {
        int n = threadIdx.y + j * 8;
        int kk = k0 + threadIdx.x;
        Wt[(size_t)(n0 + n) * K + (kk & ~31) + kperm32(kk & 31)] =
            __float2bfloat16_rn(t[threadIdx.x][n]);
    }
}

// ---------------------------------------------------------------------------
extern "C" void kernel_launch(void* const* d_in, const int* in_sizes, int n_in,
                              void* d_out, int out_size)
{
    const float* x  = (const float*)d_in[0];
    const float* W1 = (const float*)d_in[2];
    const float* b1 = (const float*)d_in[3];
    const float* W2 = (const float*)d_in[4];
    const float* b2 = (const float*)d_in[5];
    const float* W3 = (const float*)d_in[6];
    const float* b3 = (const float*)d_in[7];
    float* out = (float*)d_out;

    __nv_bfloat16 *xm, *h1, *h2, *w1t, *w2t, *w3t;
    cudaGetSymbolAddress((void**)&xm,  g_xm);
    cudaGetSymbolAddress((void**)&h1,  g_h1);
    cudaGetSymbolAddress((void**)&h2,  g_h2);
    cudaGetSymbolAddress((void**)&w1t, g_w1t);
    cudaGetSymbolAddress((void**)&w2t, g_w2t);
    cudaGetSymbolAddress((void**)&w3t, g_w3t);

    cudaFuncSetAttribute(gemm_bf16<0>, cudaFuncAttributeMaxDynamicSharedMemorySize, SMEM_DYN);
    cudaFuncSetAttribute(gemm_bf16<1>, cudaFuncAttributeMaxDynamicSharedMemorySize, SMEM_DYN);

    // all weight packs in one launch (grid sized for W3: 3072/32 x 1024/32)
    transpose_all_kernel<<<dim3(D_OUT / 32, D_H2 / 32, 3), dim3(32, 8)>>>(W1, W2, W3);

    // masked input (bf16, K-perm)
    mask_build_kernel<<<BATCH / 8, 256>>>(x);

    // h1 = relu(xm @ W1 + b1), bf16 K-permuted   [32768,512] K=160 (KT=5)
    gemm_bf16<0><<<(BATCH / BM) * (D_H1 / BN), 128, SMEM_DYN>>>(
        xm, w1t, b1, h1, BATCH, D_H1, D_IN);

    // h2 = relu(h1 @ W2 + b2), bf16 K-permuted
    gemm_bf16<0><<<(BATCH / BM) * (D_H2 / BN), 128, SMEM_DYN>>>(
        h1, w2t, b2, h2, BATCH, D_H2, D_H1);

    // out = sigmoid(h2 @ W3 + b3), fp32
    gemm_bf16<1><<<(BATCH / BM) * (D_OUT / BN), 128, SMEM_DYN>>>(
        h2, w3t, b3, out, BATCH, D_OUT, D_H2);
}